// round 2
// baseline (speedup 1.0000x reference)
#include <cuda_runtime.h>
#include <math.h>

// Problem constants
#define VSZ  32000
#define ED   512
#define HD   1024
#define NBATCH 32
#define TT   256
#define NS   255              // time steps (T-1)
#define MR   (NS*NBATCH)      // 8160 rows of the batched time-major matrices
#define G3   (3*HD)           // 3072
#define NPART 500             // vocab tiles (32000/64)

// -------- device scratch (static __device__ arrays: allocation-free) --------
__device__ float g_GI[MR * G3];          // input-gate preactivations  (~100 MB)
__device__ float g_Hall[MR * HD];        // all hidden states h_t      (~33 MB)
__device__ float g_GH[2 * G3 * NBATCH];  // per-step gh, split-K halves
__device__ float g_TGT[MR];              // target logits
__device__ float g_SUMEXP[MR];           // sum_v exp(logit)
__device__ float g_PART[MR * NPART];     // per-vocab-tile exp partial sums

__device__ __forceinline__ float sigmoidf_(float x) {
    return 1.0f / (1.0f + expf(-x));
}

// ============================================================================
// Kernel 1: GI[m, r] = b_ih[r] + emb(words[m]) . w_ih[r, :]
//   m = t*32 + n,  t in [0,255), uses words[n, t]   (x_t = emb[:, :-1])
//   Tiled fp32 GEMM, A gathered from embedding table. BM=64 BN=64 BK=32.
// ============================================================================
__global__ void gi_kernel(const int* __restrict__ words,
                          const float* __restrict__ embed_w,
                          const float* __restrict__ w_ih,
                          const float* __restrict__ b_ih)
{
    __shared__ float As[32][68];
    __shared__ float Ws[32][68];
    __shared__ int   rowbase[64];

    const int tid = threadIdx.x;
    const int m0 = blockIdx.y * 64;
    const int n0 = blockIdx.x * 64;

    if (tid < 64) {
        int m = m0 + tid;
        int base = 0;
        if (m < MR) {
            int t = m >> 5, n = m & 31;
            base = words[n * TT + t] * ED;
        }
        rowbase[tid] = base;
    }
    __syncthreads();

    const int ty = tid >> 4, tx = tid & 15;
    float acc[4][4];
#pragma unroll
    for (int i = 0; i < 4; i++)
#pragma unroll
        for (int j = 0; j < 4; j++) acc[i][j] = 0.0f;

    for (int kt = 0; kt < ED; kt += 32) {
#pragma unroll
        for (int i = 0; i < 8; i++) {
            int idx = tid + i * 256;
            int k = idx & 31, mm = idx >> 5;
            As[k][mm] = embed_w[rowbase[mm] + kt + k];
            Ws[k][mm] = w_ih[(n0 + mm) * ED + kt + k];
        }
        __syncthreads();
#pragma unroll
        for (int k = 0; k < 32; k++) {
            float4 av = *(const float4*)&As[k][ty * 4];
            float4 bv = *(const float4*)&Ws[k][tx * 4];
            float a_[4] = {av.x, av.y, av.z, av.w};
            float b_[4] = {bv.x, bv.y, bv.z, bv.w};
#pragma unroll
            for (int i = 0; i < 4; i++)
#pragma unroll
                for (int j = 0; j < 4; j++) acc[i][j] += a_[i] * b_[j];
        }
        __syncthreads();
    }

#pragma unroll
    for (int i = 0; i < 4; i++) {
        int m = m0 + ty * 4 + i;
        if (m < MR) {
#pragma unroll
            for (int j = 0; j < 4; j++) {
                int c = n0 + tx * 4 + j;
                g_GI[m * G3 + c] = acc[i][j] + b_ih[c];
            }
        }
    }
}

// ============================================================================
// Kernel 2 (per step): GH[kh][r, n] = sum over K-half of w_hh[r,:] . h_prev[n,:]
//   BM=32 BN=32 BK=32, split-K=2 (grid.y) for parallelism (192 blocks).
// ============================================================================
__global__ void gh_kernel(const float* __restrict__ hidden0,
                          const float* __restrict__ w_hh,
                          int t)
{
    const float* h_prev = (t == 0) ? hidden0 : &g_Hall[(t - 1) * NBATCH * HD];

    __shared__ float As[32][34];
    __shared__ float Bs[32][34];

    const int tid = threadIdx.x;
    const int m0 = blockIdx.x * 32;     // row tile in [0, 3072)
    const int kh = blockIdx.y;          // K half
    const int kbase = kh * 512;
    const int ty = tid >> 4, tx = tid & 15;

    float acc00 = 0.f, acc01 = 0.f, acc10 = 0.f, acc11 = 0.f;

    for (int kt = 0; kt < 512; kt += 32) {
#pragma unroll
        for (int i = 0; i < 4; i++) {
            int idx = tid + i * 256;
            int k = idx & 31, r = idx >> 5;
            As[k][r] = w_hh[(m0 + r) * HD + kbase + kt + k];
            Bs[k][r] = h_prev[r * HD + kbase + kt + k];
        }
        __syncthreads();
#pragma unroll
        for (int k = 0; k < 32; k++) {
            float2 a = *(const float2*)&As[k][ty * 2];
            float2 b = *(const float2*)&Bs[k][tx * 2];
            acc00 += a.x * b.x; acc01 += a.x * b.y;
            acc10 += a.y * b.x; acc11 += a.y * b.y;
        }
        __syncthreads();
    }

    float* dst = &g_GH[kh * (G3 * NBATCH)];
    int r0 = m0 + ty * 2, c0 = tx * 2;
    dst[(r0    ) * NBATCH + c0    ] = acc00;
    dst[(r0    ) * NBATCH + c0 + 1] = acc01;
    dst[(r0 + 1) * NBATCH + c0    ] = acc10;
    dst[(r0 + 1) * NBATCH + c0 + 1] = acc11;
}

// ============================================================================
// Kernel 3 (per step): GRU gate math -> h_t written to g_Hall[t]
// ============================================================================
__global__ void gate_kernel(const float* __restrict__ hidden0,
                            const float* __restrict__ b_hh,
                            int t)
{
    const float* h_prev = (t == 0) ? hidden0 : &g_Hall[(t - 1) * NBATCH * HD];
    int gid = blockIdx.x * 256 + threadIdx.x;   // 0..32767
    int n = gid >> 10, j = gid & 1023;
    int m = t * NBATCH + n;

    const float* gi = &g_GI[m * G3];
    float gir = gi[j];
    float giz = gi[HD + j];
    float gin = gi[2 * HD + j];

    const float* gh0 = g_GH;
    const float* gh1 = g_GH + G3 * NBATCH;
    float ghr = gh0[(j         ) * NBATCH + n] + gh1[(j         ) * NBATCH + n] + b_hh[j];
    float ghz = gh0[(HD + j    ) * NBATCH + n] + gh1[(HD + j    ) * NBATCH + n] + b_hh[HD + j];
    float ghn = gh0[(2 * HD + j) * NBATCH + n] + gh1[(2 * HD + j) * NBATCH + n] + b_hh[2 * HD + j];

    float r  = sigmoidf_(gir + ghr);
    float z  = sigmoidf_(giz + ghz);
    float nn = tanhf(gin + r * ghn);
    float hp = h_prev[n * HD + j];

    g_Hall[m * HD + j] = (1.0f - z) * nn + z * hp;
}

// ============================================================================
// Kernel 4: emit GEMM + exp row-sum epilogue.
//   logits[m, v] = Hall[m,:] . emit_w[v,:] + emit_b[v]
//   g_PART[m, vtile] = sum_{v in tile} exp(logit)   (deterministic reduce later)
//   |logit| <= 32 so no max-subtraction needed in fp32.
//   BM=64 BN=64 BK=32.
// ============================================================================
__global__ void emit_kernel(const float* __restrict__ emit_w,
                            const float* __restrict__ emit_b)
{
    __shared__ float As[32][68];
    __shared__ float Ws[32][68];
    __shared__ float red[64][17];

    const int tid = threadIdx.x;
    const int m0 = blockIdx.y * 64;
    const int n0 = blockIdx.x * 64;
    const int ty = tid >> 4, tx = tid & 15;

    float acc[4][4];
#pragma unroll
    for (int i = 0; i < 4; i++)
#pragma unroll
        for (int j = 0; j < 4; j++) acc[i][j] = 0.0f;

    for (int kt = 0; kt < HD; kt += 32) {
#pragma unroll
        for (int i = 0; i < 8; i++) {
            int idx = tid + i * 256;
            int k = idx & 31, mm = idx >> 5;
            int m = m0 + mm;
            As[k][mm] = (m < MR) ? g_Hall[m * HD + kt + k] : 0.0f;
            Ws[k][mm] = emit_w[(n0 + mm) * HD + kt + k];
        }
        __syncthreads();
#pragma unroll
        for (int k = 0; k < 32; k++) {
            float4 av = *(const float4*)&As[k][ty * 4];
            float4 bv = *(const float4*)&Ws[k][tx * 4];
            float a_[4] = {av.x, av.y, av.z, av.w};
            float b_[4] = {bv.x, bv.y, bv.z, bv.w};
#pragma unroll
            for (int i = 0; i < 4; i++)
#pragma unroll
                for (int j = 0; j < 4; j++) acc[i][j] += a_[i] * b_[j];
        }
        __syncthreads();
    }

    // exp + per-thread row partials
#pragma unroll
    for (int i = 0; i < 4; i++) {
        float s = 0.0f;
#pragma unroll
        for (int j = 0; j < 4; j++) {
            int c = n0 + tx * 4 + j;
            s += __expf(acc[i][j] + emit_b[c]);
        }
        red[ty * 4 + i][tx] = s;
    }
    __syncthreads();
    if (tid < 64) {
        float s = 0.0f;
#pragma unroll
        for (int x = 0; x < 16; x++) s += red[tid][x];
        int m = m0 + tid;
        if (m < MR) g_PART[m * NPART + blockIdx.x] = s;
    }
}

// ============================================================================
// Kernel 5: target logits. One warp per row m: dot(Hall[m], emit_w[target]).
//   target at step t is words[n, t+1].
// ============================================================================
__global__ void tgt_kernel(const int* __restrict__ words,
                           const float* __restrict__ emit_w,
                           const float* __restrict__ emit_b)
{
    int warp = threadIdx.x >> 5, lane = threadIdx.x & 31;
    int m = blockIdx.x * 8 + warp;          // 1020*8 = 8160 exact
    int t = m >> 5, n = m & 31;
    int w = words[n * TT + t + 1];
    const float* h  = &g_Hall[m * HD];
    const float* wr = &emit_w[w * HD];
    float s = 0.0f;
    for (int k = lane; k < HD; k += 32) s += h[k] * wr[k];
#pragma unroll
    for (int o = 16; o; o >>= 1) s += __shfl_down_sync(0xffffffffu, s, o);
    if (lane == 0) g_TGT[m] = s + emit_b[w];
}

// Kernel 6: reduce exp partials (fixed order -> deterministic)
__global__ void lse_kernel()
{
    int warp = threadIdx.x >> 5, lane = threadIdx.x & 31;
    int m = blockIdx.x * 8 + warp;
    float s = 0.0f;
    for (int i = lane; i < NPART; i += 32) s += g_PART[m * NPART + i];
#pragma unroll
    for (int o = 16; o; o >>= 1) s += __shfl_down_sync(0xffffffffu, s, o);
    if (lane == 0) g_SUMEXP[m] = s;
}

// Kernel 7: word_marginals[n] = sum_t ( tgt - log(sumexp) )
__global__ void marg_kernel(float* __restrict__ out)
{
    __shared__ float red[256];
    int n = blockIdx.x, tid = threadIdx.x;
    float s = 0.0f;
    if (tid < NS) {
        int m = tid * NBATCH + n;
        s = g_TGT[m] - logf(g_SUMEXP[m]);
    }
    red[tid] = s;
    __syncthreads();
    for (int o = 128; o; o >>= 1) {
        if (tid < o) red[tid] += red[tid + o];
        __syncthreads();
    }
    if (tid == 0) out[n] = red[0];
}

// Kernel 8: h_final = Hall[last step]
__global__ void hfinal_kernel(float* __restrict__ out)
{
    int gid = blockIdx.x * 256 + threadIdx.x;   // 0..32767
    out[NBATCH + gid] = g_Hall[(NS - 1) * NBATCH * HD + gid];
}

// ============================================================================
// Launch: graph-capturable, allocation-free, deterministic.
// Inputs (metadata order): words, hidden_state, embed_w, w_ih, w_hh,
//                          b_ih, b_hh, emit_w, emit_b
// Output: word_marginals[32] then h_final[32*1024]
// ============================================================================
extern "C" void kernel_launch(void* const* d_in, const int* in_sizes, int n_in,
                              void* d_out, int out_size)
{
    (void)in_sizes; (void)n_in; (void)out_size;
    const int*   words   = (const int*)  d_in[0];
    const float* hidden  = (const float*)d_in[1];
    const float* embed_w = (const float*)d_in[2];
    const float* w_ih    = (const float*)d_in[3];
    const float* w_hh    = (const float*)d_in[4];
    const float* b_ih    = (const float*)d_in[5];
    const float* b_hh    = (const float*)d_in[6];
    const float* emit_w  = (const float*)d_in[7];
    const float* emit_b  = (const float*)d_in[8];
    float* out = (float*)d_out;

    // Phase 0: all input-gate preactivations in one GEMM (hoisted from loop)
    gi_kernel<<<dim3(48, 128), 256>>>(words, embed_w, w_ih, b_ih);

    // Phase 1: sequential GRU recurrence
    for (int t = 0; t < NS; t++) {
        gh_kernel<<<dim3(96, 2), 256>>>(hidden, w_hh, t);
        gate_kernel<<<128, 256>>>(hidden, b_hh, t);
    }

    // Phase 2: batched emit GEMM + logsumexp + targets
    emit_kernel<<<dim3(NPART, 128), 256>>>(emit_w, emit_b);
    tgt_kernel<<<1020, 256>>>(words, emit_w, emit_b);
    lse_kernel<<<1020, 256>>>();

    // Phase 3: outputs
    marg_kernel<<<NBATCH, 256>>>(out);
    hfinal_kernel<<<128, 256>>>(out);
}

// round 4
// speedup vs baseline: 3.1499x; 3.1499x over previous
#include <cuda_runtime.h>
#include <cuda_bf16.h>
#include <math.h>
#include <stdint.h>

// Problem constants
#define VSZ  32000
#define ED   512
#define HD   1024
#define NBATCH 32
#define TT   256
#define NS   255              // time steps (T-1)
#define MR   (NS*NBATCH)      // 8160
#define MPAD 8192             // padded rows for tensor-core emit
#define G3   (3*HD)           // 3072
#define NPART 250             // vocab tiles of 128 (32000/128)
#define GHK  4                // gh split-K parts

// -------- device scratch (static __device__ arrays: allocation-free) --------
__device__ float g_GI[MR * G3];                 // input-gate preactivations
__device__ float g_Hall[MR * HD];               // all hidden states (fp32)
__device__ float g_GH[GHK * G3 * NBATCH];       // per-step gh split-K parts
__device__ float g_TGT[MR];                     // target logits (fp32)
__device__ float g_SUMEXP[MR];                  // sum_v exp(logit)
__device__ float g_PART[(size_t)MR * NPART];    // per-vocab-tile exp partials
__device__ __nv_bfloat16 g_Hbf[(size_t)MPAD * HD];   // Hall in bf16 (padded)
__device__ __nv_bfloat16 g_Wbf[(size_t)VSZ * HD];    // emit_w in bf16

__device__ __forceinline__ float sigmoidf_(float x) {
    return 1.0f / (1.0f + expf(-x));
}

// ====================== PTX helpers (sm_80+ baseline, no target gates) =====
__device__ __forceinline__ uint32_t smem_u32(const void* p) {
    uint32_t a;
    asm("{ .reg .u64 t; cvta.to.shared.u64 t, %1; cvt.u32.u64 %0, t; }" : "=r"(a) : "l"(p));
    return a;
}
__device__ __forceinline__ void cp_async16(uint32_t s, const void* g) {
    asm volatile("cp.async.cg.shared.global [%0], [%1], 16;" :: "r"(s), "l"(g) : "memory");
}
#define CP_COMMIT()  asm volatile("cp.async.commit_group;" ::: "memory")
#define CP_WAIT0()   asm volatile("cp.async.wait_group 0;" ::: "memory")
#define CP_WAIT1()   asm volatile("cp.async.wait_group 1;" ::: "memory")

__device__ __forceinline__ void ldsm_x4(uint32_t& r0, uint32_t& r1, uint32_t& r2, uint32_t& r3,
                                        uint32_t addr) {
    asm volatile("ldmatrix.sync.aligned.m8n8.x4.shared.b16 {%0,%1,%2,%3}, [%4];"
                 : "=r"(r0), "=r"(r1), "=r"(r2), "=r"(r3) : "r"(addr));
}
__device__ __forceinline__ void mma_bf16(float* c, uint32_t a0, uint32_t a1, uint32_t a2,
                                         uint32_t a3, uint32_t b0, uint32_t b1) {
    asm volatile(
        "mma.sync.aligned.m16n8k16.row.col.f32.bf16.bf16.f32 "
        "{%0,%1,%2,%3}, {%4,%5,%6,%7}, {%8,%9}, {%0,%1,%2,%3};"
        : "+f"(c[0]), "+f"(c[1]), "+f"(c[2]), "+f"(c[3])
        : "r"(a0), "r"(a1), "r"(a2), "r"(a3), "r"(b0), "r"(b1));
}

// ============================================================================
// Kernel 1: GI[m, r] = b_ih[r] + emb(words[m]) . w_ih[r, :]   (fp32 GEMM)
// ============================================================================
__global__ void gi_kernel(const int* __restrict__ words,
                          const float* __restrict__ embed_w,
                          const float* __restrict__ w_ih,
                          const float* __restrict__ b_ih)
{
    __shared__ float As[32][68];
    __shared__ float Ws[32][68];
    __shared__ int   rowbase[64];

    const int tid = threadIdx.x;
    const int m0 = blockIdx.y * 64;
    const int n0 = blockIdx.x * 64;

    if (tid < 64) {
        int m = m0 + tid;
        int base = 0;
        if (m < MR) {
            int t = m >> 5, n = m & 31;
            base = words[n * TT + t] * ED;
        }
        rowbase[tid] = base;
    }
    __syncthreads();

    const int ty = tid >> 4, tx = tid & 15;
    float acc[4][4];
#pragma unroll
    for (int i = 0; i < 4; i++)
#pragma unroll
        for (int j = 0; j < 4; j++) acc[i][j] = 0.0f;

    for (int kt = 0; kt < ED; kt += 32) {
#pragma unroll
        for (int i = 0; i < 8; i++) {
            int idx = tid + i * 256;
            int k = idx & 31, mm = idx >> 5;
            As[k][mm] = embed_w[rowbase[mm] + kt + k];
            Ws[k][mm] = w_ih[(n0 + mm) * ED + kt + k];
        }
        __syncthreads();
#pragma unroll
        for (int k = 0; k < 32; k++) {
            float4 av = *(const float4*)&As[k][ty * 4];
            float4 bv = *(const float4*)&Ws[k][tx * 4];
            float a_[4] = {av.x, av.y, av.z, av.w};
            float b_[4] = {bv.x, bv.y, bv.z, bv.w};
#pragma unroll
            for (int i = 0; i < 4; i++)
#pragma unroll
                for (int j = 0; j < 4; j++) acc[i][j] += a_[i] * b_[j];
        }
        __syncthreads();
    }

#pragma unroll
    for (int i = 0; i < 4; i++) {
        int m = m0 + ty * 4 + i;
        if (m < MR) {
#pragma unroll
            for (int j = 0; j < 4; j++) {
                int c = n0 + tx * 4 + j;
                g_GI[m * G3 + c] = acc[i][j] + b_ih[c];
            }
        }
    }
}

// ============================================================================
// Kernel 2 (per step): GH[kh][r, n] = K-slice partial of w_hh . h_prev^T
//   BM=32 BN=32, split-K=4 (384 CTAs) for occupancy.
// ============================================================================
__global__ void gh_kernel(const float* __restrict__ hidden0,
                          const float* __restrict__ w_hh,
                          int t)
{
    const float* h_prev = (t == 0) ? hidden0 : &g_Hall[(t - 1) * NBATCH * HD];

    __shared__ float As[32][34];
    __shared__ float Bs[32][34];

    const int tid = threadIdx.x;
    const int m0 = blockIdx.x * 32;
    const int kh = blockIdx.y;
    const int kbase = kh * (HD / GHK);
    const int ty = tid >> 4, tx = tid & 15;

    float acc00 = 0.f, acc01 = 0.f, acc10 = 0.f, acc11 = 0.f;

    for (int kt = 0; kt < HD / GHK; kt += 32) {
#pragma unroll
        for (int i = 0; i < 4; i++) {
            int idx = tid + i * 256;
            int k = idx & 31, r = idx >> 5;
            As[k][r] = w_hh[(m0 + r) * HD + kbase + kt + k];
            Bs[k][r] = h_prev[r * HD + kbase + kt + k];
        }
        __syncthreads();
#pragma unroll
        for (int k = 0; k < 32; k++) {
            float2 a = *(const float2*)&As[k][ty * 2];
            float2 b = *(const float2*)&Bs[k][tx * 2];
            acc00 += a.x * b.x; acc01 += a.x * b.y;
            acc10 += a.y * b.x; acc11 += a.y * b.y;
        }
        __syncthreads();
    }

    float* dst = &g_GH[kh * (G3 * NBATCH)];
    int r0 = m0 + ty * 2, c0 = tx * 2;
    dst[(r0    ) * NBATCH + c0    ] = acc00;
    dst[(r0    ) * NBATCH + c0 + 1] = acc01;
    dst[(r0 + 1) * NBATCH + c0    ] = acc10;
    dst[(r0 + 1) * NBATCH + c0 + 1] = acc11;
}

// ============================================================================
// Kernel 3 (per step): GRU gate math -> h_t
// ============================================================================
__global__ void gate_kernel(const float* __restrict__ hidden0,
                            const float* __restrict__ b_hh,
                            int t)
{
    const float* h_prev = (t == 0) ? hidden0 : &g_Hall[(t - 1) * NBATCH * HD];
    int gid = blockIdx.x * 256 + threadIdx.x;
    int n = gid >> 10, j = gid & 1023;
    int m = t * NBATCH + n;

    const float* gi = &g_GI[m * G3];
    float gir = gi[j];
    float giz = gi[HD + j];
    float gin = gi[2 * HD + j];

    float ghr = b_hh[j], ghz = b_hh[HD + j], ghn = b_hh[2 * HD + j];
#pragma unroll
    for (int p = 0; p < GHK; p++) {
        const float* gh = &g_GH[p * (G3 * NBATCH)];
        ghr += gh[(j         ) * NBATCH + n];
        ghz += gh[(HD + j    ) * NBATCH + n];
        ghn += gh[(2 * HD + j) * NBATCH + n];
    }

    float r  = sigmoidf_(gir + ghr);
    float z  = sigmoidf_(giz + ghz);
    float nn = tanhf(gin + r * ghn);
    float hp = h_prev[n * HD + j];

    g_Hall[m * HD + j] = (1.0f - z) * nn + z * hp;
}

// ============================================================================
// Conversion kernels: fp32 -> bf16
// ============================================================================
__global__ void convH_kernel()
{
    size_t gid = (size_t)blockIdx.x * 256 + threadIdx.x;
    size_t e0 = gid * 4;
    int m = (int)(e0 >> 10);
    float4 v = make_float4(0.f, 0.f, 0.f, 0.f);
    if (m < MR) v = *(const float4*)&g_Hall[e0];
    __nv_bfloat162 p0 = __floats2bfloat162_rn(v.x, v.y);
    __nv_bfloat162 p1 = __floats2bfloat162_rn(v.z, v.w);
    uint2 packed;
    packed.x = *(const uint32_t*)&p0;
    packed.y = *(const uint32_t*)&p1;
    *(uint2*)&g_Hbf[e0] = packed;
}

__global__ void convW_kernel(const float* __restrict__ emit_w)
{
    size_t gid = (size_t)blockIdx.x * 256 + threadIdx.x;
    size_t e0 = gid * 4;
    float4 v = *(const float4*)&emit_w[e0];
    __nv_bfloat162 p0 = __floats2bfloat162_rn(v.x, v.y);
    __nv_bfloat162 p1 = __floats2bfloat162_rn(v.z, v.w);
    uint2 packed;
    packed.x = *(const uint32_t*)&p0;
    packed.y = *(const uint32_t*)&p1;
    *(uint2*)&g_Wbf[e0] = packed;
}

// ============================================================================
// Kernel 4: bf16 HMMA emit GEMM + exp row-sum epilogue (mma.sync path).
//   CTA tile: 128 M-rows x 128 vocab cols, K=1024 in 16 chunks of 64.
//   8 warps as 4(M) x 2(N); warp tile 32 x 64; m16n8k16 bf16 MMA.
//   Double-buffered cp.async; logits never leave registers.
// ============================================================================
#define EM_STAGE 32768                 // bytes per stage (A 16K + B 16K)
#define EM_BOFF  16384                 // B offset within stage
#define EM_BIAS  65536                 // bias floats (128)
#define EM_RED   66048                 // red[128][2] floats
#define EM_SMEM  67072

__global__ void __launch_bounds__(256) emit_mma_kernel(const float* __restrict__ emit_b)
{
    extern __shared__ char smem[];
    const uint32_t sb = smem_u32(smem);
    const int tid  = threadIdx.x;
    const int bn   = blockIdx.x;        // vocab tile (128 wide)
    const int m0   = blockIdx.y * 128;  // m tile (128 tall)
    const int n0   = bn * 128;

    float* bias_s = (float*)(smem + EM_BIAS);
    float* red    = (float*)(smem + EM_RED);
    if (tid < 128) bias_s[tid] = emit_b[n0 + tid];

    const char* gA = (const char*)g_Hbf + (size_t)m0 * (HD * 2);
    const char* gB = (const char*)g_Wbf + (size_t)n0 * (HD * 2);

    // ---- async tile loader: chunk c (k = c*64..c*64+63) into stage s ----
    // SMEM layout per stage: rows of 64 bf16 = 128B; granule g (16B) stored
    // at column (g ^ (row & 7)) for conflict-free cp.async + ldmatrix.
    auto load_chunk = [&](int c, int s) {
        const uint32_t aB = sb + s * EM_STAGE;
        const uint32_t bB = aB + EM_BOFF;
#pragma unroll
        for (int i = 0; i < 4; i++) {
            int idx = tid + i * 256;
            int r = idx >> 3, g = idx & 7;
            uint32_t so = (uint32_t)(r * 128 + ((g ^ (r & 7)) << 4));
            cp_async16(aB + so, gA + (size_t)r * 2048 + c * 128 + g * 16);
        }
#pragma unroll
        for (int i = 0; i < 4; i++) {
            int idx = tid + i * 256;
            int r = idx >> 3, g = idx & 7;
            uint32_t so = (uint32_t)(r * 128 + ((g ^ (r & 7)) << 4));
            cp_async16(bB + so, gB + (size_t)r * 2048 + c * 128 + g * 16);
        }
        CP_COMMIT();
    };

    // ---- warp geometry ----
    const int lane = tid & 31;
    const int w    = tid >> 5;
    const int wm   = w & 3;            // M warp: rows wm*32 .. +31
    const int wn   = w >> 2;           // N warp: cols wn*64 .. +63
    const int quad = lane >> 3;        // ldmatrix address group
    const int lrow = lane & 7;
    const int qh   = quad >> 1;        // k-halfword (0: k0-7, 1: k8-15)
    const int qr   = (quad & 1) << 3;  // row +8 within 16-tile

    // ldmatrix source rows (fixed per thread)
    int rowA[2], rowB[4];
#pragma unroll
    for (int mt = 0; mt < 2; mt++) rowA[mt] = wm * 32 + mt * 16 + qr + lrow;
#pragma unroll
    for (int np = 0; np < 4; np++) rowB[np] = wn * 64 + np * 16 + qr + lrow;

    float acc[2][8][4];
#pragma unroll
    for (int mt = 0; mt < 2; mt++)
#pragma unroll
        for (int nt = 0; nt < 8; nt++)
#pragma unroll
            for (int j = 0; j < 4; j++) acc[mt][nt][j] = 0.0f;

    // ---- pipelined mainloop ----
    load_chunk(0, 0);
    for (int c = 0; c < 16; c++) {
        if (c + 1 < 16) { load_chunk(c + 1, (c + 1) & 1); CP_WAIT1(); }
        else            { CP_WAIT0(); }
        __syncthreads();

        const uint32_t aB = sb + (c & 1) * EM_STAGE;
        const uint32_t bB = aB + EM_BOFF;
#pragma unroll
        for (int ks = 0; ks < 4; ks++) {
            uint32_t a[2][4];
#pragma unroll
            for (int mt = 0; mt < 2; mt++) {
                int r = rowA[mt];
                uint32_t off = (uint32_t)(r * 128 + (((ks * 2 + qh) ^ (r & 7)) << 4));
                ldsm_x4(a[mt][0], a[mt][1], a[mt][2], a[mt][3], aB + off);
            }
            uint32_t b[4][4];
#pragma unroll
            for (int np = 0; np < 4; np++) {
                int r = rowB[np];
                uint32_t off = (uint32_t)(r * 128 + (((ks * 2 + qh) ^ (r & 7)) << 4));
                ldsm_x4(b[np][0], b[np][1], b[np][2], b[np][3], bB + off);
            }
#pragma unroll
            for (int mt = 0; mt < 2; mt++)
#pragma unroll
                for (int np = 0; np < 4; np++)
#pragma unroll
                    for (int h = 0; h < 2; h++)
                        mma_bf16(acc[mt][2 * np + h],
                                 a[mt][0], a[mt][1], a[mt][2], a[mt][3],
                                 b[np][h], b[np][2 + h]);
        }
        __syncthreads();
    }

    // ---- epilogue: exp + row sums (rows g, g+8 of each m16 tile) ----
    const int g   = lane >> 2;
    const int cj  = (lane & 3) * 2;
#pragma unroll
    for (int mt = 0; mt < 2; mt++) {
        float s0 = 0.0f, s1 = 0.0f;
#pragma unroll
        for (int nt = 0; nt < 8; nt++) {
            int col = wn * 64 + nt * 8 + cj;
            float b0 = bias_s[col], b1 = bias_s[col + 1];
            s0 += __expf(acc[mt][nt][0] + b0) + __expf(acc[mt][nt][1] + b1);
            s1 += __expf(acc[mt][nt][2] + b0) + __expf(acc[mt][nt][3] + b1);
        }
        s0 += __shfl_xor_sync(0xffffffffu, s0, 1);
        s0 += __shfl_xor_sync(0xffffffffu, s0, 2);
        s1 += __shfl_xor_sync(0xffffffffu, s1, 1);
        s1 += __shfl_xor_sync(0xffffffffu, s1, 2);
        if ((lane & 3) == 0) {
            red[(wm * 32 + mt * 16 + g    ) * 2 + wn] = s0;
            red[(wm * 32 + mt * 16 + g + 8) * 2 + wn] = s1;
        }
    }
    __syncthreads();
    if (tid < 128) {
        int m = m0 + tid;
        if (m < MR) g_PART[(size_t)m * NPART + bn] = red[tid * 2] + red[tid * 2 + 1];
    }
}

// ============================================================================
// Kernel 5: target logits (fp32, one warp per row)
// ============================================================================
__global__ void tgt_kernel(const int* __restrict__ words,
                           const float* __restrict__ emit_w,
                           const float* __restrict__ emit_b)
{
    int warp = threadIdx.x >> 5, lane = threadIdx.x & 31;
    int m = blockIdx.x * 8 + warp;
    int t = m >> 5, n = m & 31;
    int w = words[n * TT + t + 1];
    const float* h  = &g_Hall[m * HD];
    const float* wr = &emit_w[w * HD];
    float s = 0.0f;
    for (int k = lane; k < HD; k += 32) s += h[k] * wr[k];
#pragma unroll
    for (int o = 16; o; o >>= 1) s += __shfl_down_sync(0xffffffffu, s, o);
    if (lane == 0) g_TGT[m] = s + emit_b[w];
}

// Kernel 6: reduce exp partials (fixed order -> deterministic)
__global__ void lse_kernel()
{
    int warp = threadIdx.x >> 5, lane = threadIdx.x & 31;
    int m = blockIdx.x * 8 + warp;
    float s = 0.0f;
    for (int i = lane; i < NPART; i += 32) s += g_PART[(size_t)m * NPART + i];
#pragma unroll
    for (int o = 16; o; o >>= 1) s += __shfl_down_sync(0xffffffffu, s, o);
    if (lane == 0) g_SUMEXP[m] = s;
}

// Kernel 7: word_marginals
__global__ void marg_kernel(float* __restrict__ out)
{
    __shared__ float red[256];
    int n = blockIdx.x, tid = threadIdx.x;
    float s = 0.0f;
    if (tid < NS) {
        int m = tid * NBATCH + n;
        s = g_TGT[m] - logf(g_SUMEXP[m]);
    }
    red[tid] = s;
    __syncthreads();
    for (int o = 128; o; o >>= 1) {
        if (tid < o) red[tid] += red[tid + o];
        __syncthreads();
    }
    if (tid == 0) out[n] = red[0];
}

// Kernel 8: h_final
__global__ void hfinal_kernel(float* __restrict__ out)
{
    int gid = blockIdx.x * 256 + threadIdx.x;
    out[NBATCH + gid] = g_Hall[(NS - 1) * NBATCH * HD + gid];
}

// ============================================================================
// Launch
// ============================================================================
extern "C" void kernel_launch(void* const* d_in, const int* in_sizes, int n_in,
                              void* d_out, int out_size)
{
    (void)in_sizes; (void)n_in; (void)out_size;
    const int*   words   = (const int*)  d_in[0];
    const float* hidden  = (const float*)d_in[1];
    const float* embed_w = (const float*)d_in[2];
    const float* w_ih    = (const float*)d_in[3];
    const float* w_hh    = (const float*)d_in[4];
    const float* b_ih    = (const float*)d_in[5];
    const float* b_hh    = (const float*)d_in[6];
    const float* emit_w  = (const float*)d_in[7];
    const float* emit_b  = (const float*)d_in[8];
    float* out = (float*)d_out;

    cudaFuncSetAttribute(emit_mma_kernel,
                         cudaFuncAttributeMaxDynamicSharedMemorySize, EM_SMEM);

    // Phase 0: input-gate GEMM + weight conversion
    gi_kernel<<<dim3(48, 128), 256>>>(words, embed_w, w_ih, b_ih);
    convW_kernel<<<VSZ * HD / (4 * 256), 256>>>(emit_w);

    // Phase 1: sequential GRU recurrence (fp32)
    for (int t = 0; t < NS; t++) {
        gh_kernel<<<dim3(96, GHK), 256>>>(hidden, w_hh, t);
        gate_kernel<<<128, 256>>>(hidden, b_hh, t);
    }

    // Phase 2: bf16 conversion + HMMA emit GEMM + logsumexp + targets
    convH_kernel<<<MPAD * HD / (4 * 256), 256>>>();
    emit_mma_kernel<<<dim3(NPART, MPAD / 128), 256, EM_SMEM>>>(emit_b);
    tgt_kernel<<<1020, 256>>>(words, emit_w, emit_b);
    lse_kernel<<<1020, 256>>>();

    // Phase 3: outputs
    marg_kernel<<<NBATCH, 256>>>(out);
    hfinal_kernel<<<128, 256>>>(out);
}

// round 10
// speedup vs baseline: 4.3242x; 1.3728x over previous
#include <cuda_runtime.h>
#include <cuda_bf16.h>
#include <math.h>
#include <stdint.h>

// Problem constants
#define VSZ  32000
#define ED   512
#define HD   1024
#define NBATCH 32
#define TT   256
#define NS   255              // time steps (T-1)
#define MR   (NS*NBATCH)      // 8160
#define MPAD 8192             // padded rows for tensor-core emit
#define G3   (3*HD)           // 3072
#define NPART 250             // vocab tiles of 128 (32000/128)

// Persistent recurrence config
#define NCTA 128              // 1 CTA/SM guaranteed resident (<=148)
#define JPC  8                // hidden units per CTA (1024/128)
#define RS   1026             // padded row stride (floats); RS%4==2 -> float2-only SMEM access!
#define SCRS 25               // scratch stride (floats), odd -> conflict-free

// -------- device scratch (static __device__ arrays: allocation-free) --------
__device__ float g_GI[MR * G3];                 // input-gate preactivations
__device__ float g_Hall[MR * HD];               // all hidden states (fp32)
__device__ float g_TGT[MR];                     // target logits (fp32)
__device__ float g_SUMEXP[MR];                  // sum_v exp(logit)
__device__ float g_PART[(size_t)MR * NPART];    // per-vocab-tile exp partials
__device__ __nv_bfloat16 g_Hbf[(size_t)MPAD * HD];   // Hall in bf16 (padded)
__device__ __nv_bfloat16 g_Wbf[(size_t)VSZ * HD];    // emit_w in bf16
__device__ unsigned g_bcnt;                     // barrier arrival counter
__device__ volatile unsigned g_bsense;          // barrier sense flag

__device__ __forceinline__ float sigmoidf_(float x) {
    return 1.0f / (1.0f + expf(-x));
}

// ====================== PTX helpers (sm_80+ baseline) ======================
__device__ __forceinline__ uint32_t smem_u32(const void* p) {
    uint32_t a;
    asm("{ .reg .u64 t; cvta.to.shared.u64 t, %1; cvt.u32.u64 %0, t; }" : "=r"(a) : "l"(p));
    return a;
}
__device__ __forceinline__ void cp_async16(uint32_t s, const void* g) {
    asm volatile("cp.async.cg.shared.global [%0], [%1], 16;" :: "r"(s), "l"(g) : "memory");
}
#define CP_COMMIT()  asm volatile("cp.async.commit_group;" ::: "memory")
#define CP_WAIT0()   asm volatile("cp.async.wait_group 0;" ::: "memory")
#define CP_WAIT1()   asm volatile("cp.async.wait_group 1;" ::: "memory")

__device__ __forceinline__ void ldsm_x4(uint32_t& r0, uint32_t& r1, uint32_t& r2, uint32_t& r3,
                                        uint32_t addr) {
    asm volatile("ldmatrix.sync.aligned.m8n8.x4.shared.b16 {%0,%1,%2,%3}, [%4];"
                 : "=r"(r0), "=r"(r1), "=r"(r2), "=r"(r3) : "r"(addr));
}
__device__ __forceinline__ void mma_bf16(float* c, uint32_t a0, uint32_t a1, uint32_t a2,
                                         uint32_t a3, uint32_t b0, uint32_t b1) {
    asm volatile(
        "mma.sync.aligned.m16n8k16.row.col.f32.bf16.bf16.f32 "
        "{%0,%1,%2,%3}, {%4,%5,%6,%7}, {%8,%9}, {%0,%1,%2,%3};"
        : "+f"(c[0]), "+f"(c[1]), "+f"(c[2]), "+f"(c[3])
        : "r"(a0), "r"(a1), "r"(a2), "r"(a3), "r"(b0), "r"(b1));
}

// ============================================================================
// Kernel 1: GI[m, r] = b_ih[r] + emb(words[m]) . w_ih[r, :]   (fp32 GEMM)
// ============================================================================
__global__ void gi_kernel(const int* __restrict__ words,
                          const float* __restrict__ embed_w,
                          const float* __restrict__ w_ih,
                          const float* __restrict__ b_ih)
{
    __shared__ float As[32][68];
    __shared__ float Ws[32][68];
    __shared__ int   rowbase[64];

    const int tid = threadIdx.x;
    const int m0 = blockIdx.y * 64;
    const int n0 = blockIdx.x * 64;

    if (tid < 64) {
        int m = m0 + tid;
        int base = 0;
        if (m < MR) {
            int t = m >> 5, n = m & 31;
            base = words[n * TT + t] * ED;
        }
        rowbase[tid] = base;
    }
    __syncthreads();

    const int ty = tid >> 4, tx = tid & 15;
    float acc[4][4];
#pragma unroll
    for (int i = 0; i < 4; i++)
#pragma unroll
        for (int j = 0; j < 4; j++) acc[i][j] = 0.0f;

    for (int kt = 0; kt < ED; kt += 32) {
#pragma unroll
        for (int i = 0; i < 8; i++) {
            int idx = tid + i * 256;
            int k = idx & 31, mm = idx >> 5;
            As[k][mm] = embed_w[rowbase[mm] + kt + k];
            Ws[k][mm] = w_ih[(n0 + mm) * ED + kt + k];
        }
        __syncthreads();
#pragma unroll
        for (int k = 0; k < 32; k++) {
            float4 av = *(const float4*)&As[k][ty * 4];
            float4 bv = *(const float4*)&Ws[k][tx * 4];
            float a_[4] = {av.x, av.y, av.z, av.w};
            float b_[4] = {bv.x, bv.y, bv.z, bv.w};
#pragma unroll
            for (int i = 0; i < 4; i++)
#pragma unroll
                for (int j = 0; j < 4; j++) acc[i][j] += a_[i] * b_[j];
        }
        __syncthreads();
    }

#pragma unroll
    for (int i = 0; i < 4; i++) {
        int m = m0 + ty * 4 + i;
        if (m < MR) {
#pragma unroll
            for (int j = 0; j < 4; j++) {
                int c = n0 + tx * 4 + j;
                g_GI[m * G3 + c] = acc[i][j] + b_ih[c];
            }
        }
    }
}

// ============================================================================
// Kernel 2: PERSISTENT fused GRU recurrence.
//   128 CTAs x 256 threads, each CTA owns JPC=8 hidden units j.
//   w_hh slice (24 rows x 1024) lives in SMEM for all 255 steps.
//   NOTE: RS % 4 == 2 -> ALL SMEM tile accesses must be float2/scalar
//   (float4 at row offsets would be misaligned -> HW trap).
// ============================================================================
__device__ __forceinline__ void grid_barrier(int tid, unsigned ns) {
    __syncthreads();
    if (tid == 0) {
        __threadfence();
        if (atomicAdd(&g_bcnt, 1) == NCTA - 1) {
            atomicExch(&g_bcnt, 0);
            __threadfence();
            g_bsense = ns;
        } else {
            while (g_bsense != ns) __nanosleep(32);
        }
        __threadfence();
    }
    __syncthreads();
}

__global__ void __launch_bounds__(256, 1) rnn_persist_kernel(
    const float* __restrict__ hidden0,
    const float* __restrict__ w_hh,
    const float* __restrict__ b_hh)
{
    extern __shared__ float sm[];
    float* w_s = sm;                 // 24 * RS floats
    float* h_s = sm + 24 * RS;       // 32 * RS floats (also reused as scratch)

    const int tid = threadIdx.x;
    const int j0  = blockIdx.x * JPC;

    // ---- load w_hh slice once: rows {g*1024 + j0+jj : g<3, jj<8} ----
    // global float4 load (16B-aligned), SMEM stores as 2x float2 (RS%4==2)
#pragma unroll
    for (int it = 0; it < 24; it++) {
        int idx = tid + it * 256;            // float4 granule, 24*256 total
        int r = idx >> 8;                    // 0..23 (g*8+jj)
        int q = idx & 255;
        int grow = (r >> 3) * HD + j0 + (r & 7);
        float4 v = *(const float4*)&w_hh[(size_t)grow * HD + q * 4];
        float* d = &w_s[r * RS + q * 4];
        *(float2*)&d[0] = make_float2(v.x, v.y);
        *(float2*)&d[2] = make_float2(v.z, v.w);
    }

    // compute-thread identity: jjblk(2b) | nblk(3b) | ks(3b)
    const int jjblk = tid & 3;
    const int nblk  = (tid >> 2) & 7;
    const int ks    = tid >> 5;
    const int kbase = ks * 128;

    // combiner identity: (n_o, jj_o) output element
    const int n_o  = tid >> 3;
    const int jj_o = tid & 7;
    const int s_jj = jj_o >> 1, s_u = jj_o & 1, s_nb = n_o >> 2, s_i = n_o & 3;
    const float bh_r = b_hh[j0 + jj_o];
    const float bh_z = b_hh[HD + j0 + jj_o];
    const float bh_n = b_hh[2 * HD + j0 + jj_o];

    unsigned sense = 0;

    for (int t = 0; t < NS; t++) {
        // ---- stage h_{t-1} into SMEM (float4 global -> 2x float2 smem) ----
        const float* hsrc = (t == 0) ? hidden0 : &g_Hall[(size_t)(t - 1) * NBATCH * HD];
#pragma unroll
        for (int it = 0; it < 32; it++) {
            int idx = tid + it * 256;        // 8192 float4
            int n = idx >> 8;
            int q = idx & 255;
            float4 v = *(const float4*)&hsrc[n * HD + q * 4];
            float* d = &h_s[n * RS + q * 4];
            *(float2*)&d[0] = make_float2(v.x, v.y);
            *(float2*)&d[2] = make_float2(v.z, v.w);
        }
        __syncthreads();

        // ---- register-tiled partial dots: 3 gates x 2 jj x 4 n over K/8 ----
        float acc[3][2][4];
#pragma unroll
        for (int g = 0; g < 3; g++)
#pragma unroll
            for (int u = 0; u < 2; u++)
#pragma unroll
                for (int i = 0; i < 4; i++) acc[g][u][i] = 0.0f;

        {
            const float* hb = &h_s[nblk * 4 * RS + kbase];
            const float* wb = &w_s[jjblk * 2 * RS + kbase];
#pragma unroll 4
            for (int q = 0; q < 64; q++) {
                int ko = q * 2;
                float2 hv[4];
#pragma unroll
                for (int i = 0; i < 4; i++)
                    hv[i] = *(const float2*)&hb[i * RS + ko];
#pragma unroll
                for (int g = 0; g < 3; g++) {
#pragma unroll
                    for (int u = 0; u < 2; u++) {
                        float2 wv = *(const float2*)&wb[(g * 8 + u) * RS + ko];
#pragma unroll
                        for (int i = 0; i < 4; i++) {
                            acc[g][u][i] = fmaf(wv.x, hv[i].x, acc[g][u][i]);
                            acc[g][u][i] = fmaf(wv.y, hv[i].y, acc[g][u][i]);
                        }
                    }
                }
            }
        }

        // hp needed by combiner (read before scratch tramples h_s)
        float hp = h_s[n_o * RS + j0 + jj_o];
        __syncthreads();

        // ---- split-K reduction via SMEM scratch (overlays h_s) ----
        float* scr = h_s;
#pragma unroll
        for (int g = 0; g < 3; g++)
#pragma unroll
            for (int u = 0; u < 2; u++)
#pragma unroll
                for (int i = 0; i < 4; i++)
                    scr[tid * SCRS + g * 8 + u * 4 + i] = acc[g][u][i];
        __syncthreads();

        float gr = bh_r, gz = bh_z, gn = bh_n;
#pragma unroll
        for (int kk = 0; kk < 8; kk++) {
            int st = s_jj | (s_nb << 2) | (kk << 5);
            gr += scr[st * SCRS + 0 * 8 + s_u * 4 + s_i];
            gz += scr[st * SCRS + 1 * 8 + s_u * 4 + s_i];
            gn += scr[st * SCRS + 2 * 8 + s_u * 4 + s_i];
        }

        // ---- fused gate math + h_t writeback (fp32 + bf16) ----
        int m = t * NBATCH + n_o;
        int j = j0 + jj_o;
        const float* gi = &g_GI[(size_t)m * G3];
        float r  = sigmoidf_(gi[j] + gr);
        float z  = sigmoidf_(gi[HD + j] + gz);
        float nn = tanhf(gi[2 * HD + j] + r * gn);
        float h  = (1.0f - z) * nn + z * hp;
        g_Hall[(size_t)m * HD + j] = h;
        g_Hbf[(size_t)m * HD + j]  = __float2bfloat16(h);

        // ---- grid barrier (release h_t to all CTAs) ----
        grid_barrier(tid, sense ^ 1);
        sense ^= 1;
    }

    // parity-restoring extra barrier: 256 total -> g_bsense/g_bcnt return to 0
    grid_barrier(tid, sense ^ 1);
}

// ============================================================================
// Kernel: fp32 -> bf16 conversion of emit_w
// ============================================================================
__global__ void convW_kernel(const float* __restrict__ emit_w)
{
    size_t gid = (size_t)blockIdx.x * 256 + threadIdx.x;
    size_t e0 = gid * 4;
    float4 v = *(const float4*)&emit_w[e0];
    __nv_bfloat162 p0 = __floats2bfloat162_rn(v.x, v.y);
    __nv_bfloat162 p1 = __floats2bfloat162_rn(v.z, v.w);
    uint2 packed;
    packed.x = *(const uint32_t*)&p0;
    packed.y = *(const uint32_t*)&p1;
    *(uint2*)&g_Wbf[e0] = packed;
}

// ============================================================================
// Kernel 4: bf16 HMMA emit GEMM + exp row-sum epilogue (unchanged from R4).
// ============================================================================
#define EM_STAGE 32768
#define EM_BOFF  16384
#define EM_BIAS  65536
#define EM_RED   66048
#define EM_SMEM  67072

__global__ void __launch_bounds__(256) emit_mma_kernel(const float* __restrict__ emit_b)
{
    extern __shared__ char smem[];
    const uint32_t sb = smem_u32(smem);
    const int tid  = threadIdx.x;
    const int bn   = blockIdx.x;
    const int m0   = blockIdx.y * 128;
    const int n0   = bn * 128;

    float* bias_s = (float*)(smem + EM_BIAS);
    float* red    = (float*)(smem + EM_RED);
    if (tid < 128) bias_s[tid] = emit_b[n0 + tid];

    const char* gA = (const char*)g_Hbf + (size_t)m0 * (HD * 2);
    const char* gB = (const char*)g_Wbf + (size_t)n0 * (HD * 2);

    auto load_chunk = [&](int c, int s) {
        const uint32_t aB = sb + s * EM_STAGE;
        const uint32_t bB = aB + EM_BOFF;
#pragma unroll
        for (int i = 0; i < 4; i++) {
            int idx = tid + i * 256;
            int r = idx >> 3, g = idx & 7;
            uint32_t so = (uint32_t)(r * 128 + ((g ^ (r & 7)) << 4));
            cp_async16(aB + so, gA + (size_t)r * 2048 + c * 128 + g * 16);
        }
#pragma unroll
        for (int i = 0; i < 4; i++) {
            int idx = tid + i * 256;
            int r = idx >> 3, g = idx & 7;
            uint32_t so = (uint32_t)(r * 128 + ((g ^ (r & 7)) << 4));
            cp_async16(bB + so, gB + (size_t)r * 2048 + c * 128 + g * 16);
        }
        CP_COMMIT();
    };

    const int lane = tid & 31;
    const int w    = tid >> 5;
    const int wm   = w & 3;
    const int wn   = w >> 2;
    const int quad = lane >> 3;
    const int lrow = lane & 7;
    const int qh   = quad >> 1;
    const int qr   = (quad & 1) << 3;

    int rowA[2], rowB[4];
#pragma unroll
    for (int mt = 0; mt < 2; mt++) rowA[mt] = wm * 32 + mt * 16 + qr + lrow;
#pragma unroll
    for (int np = 0; np < 4; np++) rowB[np] = wn * 64 + np * 16 + qr + lrow;

    float acc[2][8][4];
#pragma unroll
    for (int mt = 0; mt < 2; mt++)
#pragma unroll
        for (int nt = 0; nt < 8; nt++)
#pragma unroll
            for (int j = 0; j < 4; j++) acc[mt][nt][j] = 0.0f;

    load_chunk(0, 0);
    for (int c = 0; c < 16; c++) {
        if (c + 1 < 16) { load_chunk(c + 1, (c + 1) & 1); CP_WAIT1(); }
        else            { CP_WAIT0(); }
        __syncthreads();

        const uint32_t aB = sb + (c & 1) * EM_STAGE;
        const uint32_t bB = aB + EM_BOFF;
#pragma unroll
        for (int ks = 0; ks < 4; ks++) {
            uint32_t a[2][4];
#pragma unroll
            for (int mt = 0; mt < 2; mt++) {
                int r = rowA[mt];
                uint32_t off = (uint32_t)(r * 128 + (((ks * 2 + qh) ^ (r & 7)) << 4));
                ldsm_x4(a[mt][0], a[mt][1], a[mt][2], a[mt][3], aB + off);
            }
            uint32_t b[4][4];
#pragma unroll
            for (int np = 0; np < 4; np++) {
                int r = rowB[np];
                uint32_t off = (uint32_t)(r * 128 + (((ks * 2 + qh) ^ (r & 7)) << 4));
                ldsm_x4(b[np][0], b[np][1], b[np][2], b[np][3], bB + off);
            }
#pragma unroll
            for (int mt = 0; mt < 2; mt++)
#pragma unroll
                for (int np = 0; np < 4; np++)
#pragma unroll
                    for (int h = 0; h < 2; h++)
                        mma_bf16(acc[mt][2 * np + h],
                                 a[mt][0], a[mt][1], a[mt][2], a[mt][3],
                                 b[np][h], b[np][2 + h]);
        }
        __syncthreads();
    }

    const int g   = lane >> 2;
    const int cj  = (lane & 3) * 2;
#pragma unroll
    for (int mt = 0; mt < 2; mt++) {
        float s0 = 0.0f, s1 = 0.0f;
#pragma unroll
        for (int nt = 0; nt < 8; nt++) {
            int col = wn * 64 + nt * 8 + cj;
            float b0 = bias_s[col], b1 = bias_s[col + 1];
            s0 += __expf(acc[mt][nt][0] + b0) + __expf(acc[mt][nt][1] + b1);
            s1 += __expf(acc[mt][nt][2] + b0) + __expf(acc[mt][nt][3] + b1);
        }
        s0 += __shfl_xor_sync(0xffffffffu, s0, 1);
        s0 += __shfl_xor_sync(0xffffffffu, s0, 2);
        s1 += __shfl_xor_sync(0xffffffffu, s1, 1);
        s1 += __shfl_xor_sync(0xffffffffu, s1, 2);
        if ((lane & 3) == 0) {
            red[(wm * 32 + mt * 16 + g    ) * 2 + wn] = s0;
            red[(wm * 32 + mt * 16 + g + 8) * 2 + wn] = s1;
        }
    }
    __syncthreads();
    if (tid < 128) {
        int m = m0 + tid;
        if (m < MR) g_PART[(size_t)m * NPART + bn] = red[tid * 2] + red[tid * 2 + 1];
    }
}

// ============================================================================
// Kernel 5: target logits (fp32, one warp per row)
// ============================================================================
__global__ void tgt_kernel(const int* __restrict__ words,
                           const float* __restrict__ emit_w,
                           const float* __restrict__ emit_b)
{
    int warp = threadIdx.x >> 5, lane = threadIdx.x & 31;
    int m = blockIdx.x * 8 + warp;
    int t = m >> 5, n = m & 31;
    int w = words[n * TT + t + 1];
    const float* h  = &g_Hall[m * HD];
    const float* wr = &emit_w[w * HD];
    float s = 0.0f;
    for (int k = lane; k < HD; k += 32) s += h[k] * wr[k];
#pragma unroll
    for (int o = 16; o; o >>= 1) s += __shfl_down_sync(0xffffffffu, s, o);
    if (lane == 0) g_TGT[m] = s + emit_b[w];
}

// Kernel 6: reduce exp partials (fixed order -> deterministic)
__global__ void lse_kernel()
{
    int warp = threadIdx.x >> 5, lane = threadIdx.x & 31;
    int m = blockIdx.x * 8 + warp;
    float s = 0.0f;
    for (int i = lane; i < NPART; i += 32) s += g_PART[(size_t)m * NPART + i];
#pragma unroll
    for (int o = 16; o; o >>= 1) s += __shfl_down_sync(0xffffffffu, s, o);
    if (lane == 0) g_SUMEXP[m] = s;
}

// Kernel 7: word_marginals
__global__ void marg_kernel(float* __restrict__ out)
{
    __shared__ float red[256];
    int n = blockIdx.x, tid = threadIdx.x;
    float s = 0.0f;
    if (tid < NS) {
        int m = tid * NBATCH + n;
        s = g_TGT[m] - logf(g_SUMEXP[m]);
    }
    red[tid] = s;
    __syncthreads();
    for (int o = 128; o; o >>= 1) {
        if (tid < o) red[tid] += red[tid + o];
        __syncthreads();
    }
    if (tid == 0) out[n] = red[0];
}

// Kernel 8: h_final
__global__ void hfinal_kernel(float* __restrict__ out)
{
    int gid = blockIdx.x * 256 + threadIdx.x;
    out[NBATCH + gid] = g_Hall[(NS - 1) * NBATCH * HD + gid];
}

// ============================================================================
// Launch
// ============================================================================
#define PERSIST_SMEM ((24 * RS + 32 * RS) * 4)   // 229824 bytes

extern "C" void kernel_launch(void* const* d_in, const int* in_sizes, int n_in,
                              void* d_out, int out_size)
{
    (void)in_sizes; (void)n_in; (void)out_size;
    const int*   words   = (const int*)  d_in[0];
    const float* hidden  = (const float*)d_in[1];
    const float* embed_w = (const float*)d_in[2];
    const float* w_ih    = (const float*)d_in[3];
    const float* w_hh    = (const float*)d_in[4];
    const float* b_ih    = (const float*)d_in[5];
    const float* b_hh    = (const float*)d_in[6];
    const float* emit_w  = (const float*)d_in[7];
    const float* emit_b  = (const float*)d_in[8];
    float* out = (float*)d_out;

    cudaFuncSetAttribute(emit_mma_kernel,
                         cudaFuncAttributeMaxDynamicSharedMemorySize, EM_SMEM);
    cudaFuncSetAttribute(rnn_persist_kernel,
                         cudaFuncAttributeMaxDynamicSharedMemorySize, PERSIST_SMEM);

    // Phase 0: input-gate GEMM + weight conversion
    gi_kernel<<<dim3(48, 128), 256>>>(words, embed_w, w_ih, b_ih);
    convW_kernel<<<VSZ * HD / (4 * 256), 256>>>(emit_w);

    // Phase 1: entire GRU recurrence in ONE persistent kernel
    rnn_persist_kernel<<<NCTA, 256, PERSIST_SMEM>>>(hidden, w_hh, b_hh);

    // Phase 2: HMMA emit GEMM + logsumexp + targets (h already in bf16)
    emit_mma_kernel<<<dim3(NPART, MPAD / 128), 256, EM_SMEM>>>(emit_b);
    tgt_kernel<<<1020, 256>>>(words, emit_w, emit_b);
    lse_kernel<<<1020, 256>>>();

    // Phase 3: outputs
    marg_kernel<<<NBATCH, 256>>>(out);
    hfinal_kernel<<<128, 256>>>(out);
}